// round 1
// baseline (speedup 1.0000x reference)
#include <cuda_runtime.h>

// FastRotation: for each of N volumes (5x5x5 fp32), build Rodrigues rotation
// from (theta_v[3], theta), rotate the fixed 5x5x5 [-1,1] lattice, trilinear
// sample with zero padding.
//
// Layout: 256 threads/block = 2 volumes/block, 128 threads each (125 active).
// Volume staged in shared (500B); R computed by one lane per volume into shared.

#define KDIM 5
#define KVOL 125          // 5*5*5
#define FPB  2            // filters (volumes) per block
#define TPB  (FPB * 128)

__global__ __launch_bounds__(TPB) void fast_rotation_kernel(
    const float* __restrict__ vol,      // [N,125]
    const float* __restrict__ theta_v,  // [N,3]
    const float* __restrict__ theta,    // [N]
    float* __restrict__ out,            // [N,125]
    int N)
{
    __shared__ float sv[FPB][KVOL];
    __shared__ float sR[FPB][9];

    const int t    = threadIdx.x;
    const int f    = t >> 7;          // which sub-block (0..FPB-1)
    const int lt   = t & 127;         // lane within sub-block
    const int n    = blockIdx.x * FPB + f;
    if (n >= N) return;

    // Stage volume: 125 coalesced loads
    if (lt < KVOL) sv[f][lt] = vol[(long long)n * KVOL + lt];

    // One lane per volume builds the rotation matrix
    if (lt == 0) {
        const float tx = theta_v[n * 3 + 0];
        const float ty = theta_v[n * 3 + 1];
        const float tz = theta_v[n * 3 + 2];
        const float nrm = sqrtf(tx * tx + ty * ty + tz * tz);
        const float inv = 1.0f / fmaxf(nrm, 1e-12f);
        const float vx = tx * inv, vy = ty * inv, vz = tz * inv;
        const float th = theta[n];
        const float s  = sinf(th);
        const float c  = 1.0f - cosf(th);
        const float vv = vx * vx + vy * vy + vz * vz;  // ~1, keep exact form
        // R = I + s*skew(v) + c*(v v^T - (v.v) I)
        sR[f][0] = 1.0f + c * (vx * vx - vv);
        sR[f][1] = -s * vz + c * (vx * vy);
        sR[f][2] =  s * vy + c * (vx * vz);
        sR[f][3] =  s * vz + c * (vy * vx);
        sR[f][4] = 1.0f + c * (vy * vy - vv);
        sR[f][5] = -s * vx + c * (vy * vz);
        sR[f][6] = -s * vy + c * (vz * vx);
        sR[f][7] =  s * vx + c * (vz * vy);
        sR[f][8] = 1.0f + c * (vz * vz - vv);
    }
    __syncthreads();

    if (lt >= KVOL) return;

    // Base grid point p = i*25 + j*5 + l, coords c[i] = -1 + 0.5*i
    const int i = lt / 25;
    const int j = (lt / 5) % 5;
    const int l = lt % 5;
    const float bi = 0.5f * (float)i - 1.0f;
    const float bj = 0.5f * (float)j - 1.0f;
    const float bl = 0.5f * (float)l - 1.0f;

    // grids[p,k] = sum_j base[p,j] * R[j,k]
    const float gx = bi * sR[f][0] + bj * sR[f][3] + bl * sR[f][6];
    const float gy = bi * sR[f][1] + bj * sR[f][4] + bl * sR[f][7];
    const float gz = bi * sR[f][2] + bj * sR[f][5] + bl * sR[f][8];

    // Pixel coords: (g+1)*0.5*(dim-1) with dim=5 -> (g+1)*2
    const float x = (gx + 1.0f) * 2.0f;
    const float y = (gy + 1.0f) * 2.0f;
    const float z = (gz + 1.0f) * 2.0f;

    const float x0f = floorf(x), y0f = floorf(y), z0f = floorf(z);
    const float wx = x - x0f, wy = y - y0f, wz = z - z0f;
    const int x0 = (int)x0f, y0 = (int)y0f, z0 = (int)z0f;

    float acc = 0.0f;
    #pragma unroll
    for (int dz = 0; dz < 2; ++dz) {
        const float wzc = dz ? wz : 1.0f - wz;
        const int zi = z0 + dz;
        const bool zok = (zi >= 0) & (zi < KDIM);
        const int zc = min(max(zi, 0), KDIM - 1);
        #pragma unroll
        for (int dy = 0; dy < 2; ++dy) {
            const float wyc = dy ? wy : 1.0f - wy;
            const int yi = y0 + dy;
            const bool yok = (yi >= 0) & (yi < KDIM);
            const int yc = min(max(yi, 0), KDIM - 1);
            #pragma unroll
            for (int dx = 0; dx < 2; ++dx) {
                const float wxc = dx ? wx : 1.0f - wx;
                const int xi = x0 + dx;
                const bool xok = (xi >= 0) & (xi < KDIM);
                const int xc = min(max(xi, 0), KDIM - 1);
                const float v = sv[f][zc * 25 + yc * 5 + xc];
                const float w = wzc * wyc * wxc;
                acc += (zok & yok & xok) ? w * v : 0.0f;
            }
        }
    }

    out[(long long)n * KVOL + lt] = acc;
}

extern "C" void kernel_launch(void* const* d_in, const int* in_sizes, int n_in,
                              void* d_out, int out_size)
{
    const float* vol     = (const float*)d_in[0];  // input_filter [N,5,5,5]
    const float* theta_v = (const float*)d_in[1];  // [N,3]
    const float* theta   = (const float*)d_in[2];  // [N]
    float* out = (float*)d_out;

    const int N = in_sizes[2];                     // theta has N elements
    const int blocks = (N + FPB - 1) / FPB;
    fast_rotation_kernel<<<blocks, TPB>>>(vol, theta_v, theta, out, N);
}

// round 2
// speedup vs baseline: 1.0042x; 1.0042x over previous
#include <cuda_runtime.h>

// FastRotation: per volume (5x5x5 fp32): Rodrigues rotation of the fixed
// 5x5x5 [-1,1] lattice + trilinear sampling with zero padding.
//
// Key optimization vs R1: volume staged into a zero-padded 9x9x9 shared tile
// (covers index range [-2,6] -- the full reachable trilinear footprint), so
// the 8-tap sample needs NO bounds checks / clamps / predication: one base
// address + 8 LDS at immediate offsets + 4 MUL + 8 FMA.

#define KDIM 5
#define KVOL 125
#define PD   9            // padded dim: indices -2..6
#define PAD  2
#define PSZ  (PD * PD * PD)   // 729
#define PSTR 732              // padded stride per volume (x4B = 2928B)
#define FPB  2                // volumes per block
#define TPB  (FPB * 128)

__global__ __launch_bounds__(TPB) void fast_rotation_kernel(
    const float* __restrict__ vol,      // [N,125]
    const float* __restrict__ theta_v,  // [N,3]
    const float* __restrict__ theta,    // [N]
    float* __restrict__ out,            // [N,125]
    int N)
{
    __shared__ float sp[FPB * PSTR];
    __shared__ float sR[FPB][9];

    const int t  = threadIdx.x;
    const int f  = t >> 7;           // sub-block 0..FPB-1
    const int lt = t & 127;          // lane within sub-block
    const int n  = blockIdx.x * FPB + f;

    // Zero-fill both padded tiles (all threads cooperate)
    #pragma unroll
    for (int k = t; k < FPB * PSTR; k += TPB) sp[k] = 0.0f;
    __syncthreads();

    const bool valid = (n < N);

    // Scatter volume into padded tile; lane 0 builds R
    if (valid && lt < KVOL) {
        const float v = vol[n * KVOL + lt];
        const int z = lt / 25;
        const int y = (lt / 5) % 5;
        const int x = lt % 5;
        sp[f * PSTR + (z + PAD) * (PD * PD) + (y + PAD) * PD + (x + PAD)] = v;
    }
    if (valid && lt == 0) {
        const float tx = theta_v[n * 3 + 0];
        const float ty = theta_v[n * 3 + 1];
        const float tz = theta_v[n * 3 + 2];
        const float nrm = sqrtf(tx * tx + ty * ty + tz * tz);
        const float inv = 1.0f / fmaxf(nrm, 1e-12f);
        const float vx = tx * inv, vy = ty * inv, vz = tz * inv;
        const float th = theta[n];
        const float s  = sinf(th);
        const float c  = 1.0f - cosf(th);
        const float vv = vx * vx + vy * vy + vz * vz;
        sR[f][0] = 1.0f + c * (vx * vx - vv);
        sR[f][1] = -s * vz + c * (vx * vy);
        sR[f][2] =  s * vy + c * (vx * vz);
        sR[f][3] =  s * vz + c * (vy * vx);
        sR[f][4] = 1.0f + c * (vy * vy - vv);
        sR[f][5] = -s * vx + c * (vy * vz);
        sR[f][6] = -s * vy + c * (vz * vx);
        sR[f][7] =  s * vx + c * (vz * vy);
        sR[f][8] = 1.0f + c * (vz * vz - vv);
    }
    __syncthreads();

    if (!valid || lt >= KVOL) return;

    // Base lattice coords for point p = i*25 + j*5 + l; c = -1 + 0.5*idx
    const int i = lt / 25;
    const int j = (lt / 5) % 5;
    const int l = lt % 5;
    const float bi = 0.5f * (float)i - 1.0f;
    const float bj = 0.5f * (float)j - 1.0f;
    const float bl = 0.5f * (float)l - 1.0f;

    const float R0 = sR[f][0], R1 = sR[f][1], R2 = sR[f][2];
    const float R3 = sR[f][3], R4 = sR[f][4], R5 = sR[f][5];
    const float R6 = sR[f][6], R7 = sR[f][7], R8 = sR[f][8];

    // grids[p,k] = sum_j base[p,j] * R[j,k]
    const float gx = fmaf(bi, R0, fmaf(bj, R3, bl * R6));
    const float gy = fmaf(bi, R1, fmaf(bj, R4, bl * R7));
    const float gz = fmaf(bi, R2, fmaf(bj, R5, bl * R8));

    // Pixel coords: (g+1)*0.5*(5-1) = g*2 + 2
    const float x = fmaf(gx, 2.0f, 2.0f);
    const float y = fmaf(gy, 2.0f, 2.0f);
    const float z = fmaf(gz, 2.0f, 2.0f);

    const float xf = floorf(x), yf = floorf(y), zf = floorf(z);
    const float wx = x - xf, wy = y - yf, wz = z - zf;
    const int x0 = (int)xf, y0 = (int)yf, z0 = (int)zf;

    // Padded tile base address: all 8 taps in range, zeros live in the border.
    const float* v = &sp[f * PSTR + (z0 + PAD) * (PD * PD) + (y0 + PAD) * PD + (x0 + PAD)];

    const float wx0 = 1.0f - wx, wy0 = 1.0f - wy, wz0 = 1.0f - wz;
    const float c00 = wy0 * wx0, c01 = wy0 * wx;
    const float c10 = wy  * wx0, c11 = wy  * wx;

    const float lo = fmaf(c00, v[0],  fmaf(c01, v[1],  fmaf(c10, v[PD],      c11 * v[PD + 1])));
    const float hi = fmaf(c00, v[PD*PD], fmaf(c01, v[PD*PD+1], fmaf(c10, v[PD*PD+PD], c11 * v[PD*PD+PD+1])));

    out[n * KVOL + lt] = fmaf(wz0, lo, wz * hi);
}

extern "C" void kernel_launch(void* const* d_in, const int* in_sizes, int n_in,
                              void* d_out, int out_size)
{
    const float* vol     = (const float*)d_in[0];  // input_filter [N,5,5,5]
    const float* theta_v = (const float*)d_in[1];  // [N,3]
    const float* theta   = (const float*)d_in[2];  // [N]
    float* out = (float*)d_out;

    const int N = in_sizes[2];                     // theta has N elements
    const int blocks = (N + FPB - 1) / FPB;
    fast_rotation_kernel<<<blocks, TPB>>>(vol, theta_v, theta, out, N);
}

// round 3
// speedup vs baseline: 2.2137x; 2.2045x over previous
#include <cuda_runtime.h>

// FastRotation — warp-autonomous version.
// One warp handles one 5x5x5 volume end-to-end: stage into a zero-padded
// 7x7x7 shared tile (indices -1..5), compute Rodrigues R redundantly in all
// lanes (registers only), then each lane produces 4 output points.
// No block-wide barriers; __syncwarp only. 4-way ILP per lane.

#define KVOL 125
#define PD   7
#define PP   49            // PD*PD
#define PSTR 344           // 343 rounded up to float4 multiple
#define WPB  8             // warps (= volumes) per block
#define TPB  (WPB * 32)

// Base-lattice coords per point p = i*25 + j*5 + l : c = 0.5*idx - 1
#define BV(v) (0.5f * (v) - 1.0f)
#define E4(i,j,l) {BV(i), BV(j), BV(l), 0.0f}
#define R5(i,j)  E4(i,j,0), E4(i,j,1), E4(i,j,2), E4(i,j,3), E4(i,j,4)
#define P25(i)   R5(i,0), R5(i,1), R5(i,2), R5(i,3), R5(i,4)
__device__ const float4 g_base[128] = { P25(0), P25(1), P25(2), P25(3), P25(4) };

// Scatter offset into padded tile for linear element m = z*25 + y*5 + x
#define OF(i,j,l) ((i + 1) * PP + (j + 1) * PD + (l + 1))
#define O5(i,j)  OF(i,j,0), OF(i,j,1), OF(i,j,2), OF(i,j,3), OF(i,j,4)
#define O25(i)   O5(i,0), O5(i,1), O5(i,2), O5(i,3), O5(i,4)
__device__ const int g_off[128] = { O25(0), O25(1), O25(2), O25(3), O25(4) };

__global__ __launch_bounds__(TPB) void fast_rotation_kernel(
    const float* __restrict__ vol,      // [N,125]
    const float* __restrict__ theta_v,  // [N,3]
    const float* __restrict__ theta,    // [N]
    float* __restrict__ out,            // [N,125]
    int N)
{
    __shared__ float sp[WPB * PSTR];

    const int w    = threadIdx.x >> 5;
    const int lane = threadIdx.x & 31;
    const int n    = blockIdx.x * WPB + w;
    if (n >= N) return;

    float* tile = &sp[w * PSTR];

    // Zero-fill padded tile: 86 float4 per warp
    float4* t4 = (float4*)tile;
    const float4 z4 = make_float4(0.f, 0.f, 0.f, 0.f);
    t4[lane]      = z4;
    t4[lane + 32] = z4;
    if (lane < (PSTR / 4) - 64) t4[lane + 64] = z4;
    __syncwarp();

    // Scatter volume into padded interior (coalesced global reads)
    const float* vsrc = vol + n * KVOL;
    #pragma unroll
    for (int q = 0; q < 4; ++q) {
        const int m = lane + 32 * q;
        if (m < KVOL) tile[g_off[m]] = __ldcs(vsrc + m);
    }

    // Rodrigues matrix, computed redundantly in every lane (broadcast loads).
    // Pre-scaled by 2 so pixel coord = base . (2R) + 2 directly.
    const float tx = theta_v[n * 3 + 0];
    const float ty = theta_v[n * 3 + 1];
    const float tz = theta_v[n * 3 + 2];
    const float inv = rsqrtf(fmaxf(tx * tx + ty * ty + tz * tz, 1e-24f));
    const float vx = tx * inv, vy = ty * inv, vz = tz * inv;
    const float a  = theta[n];
    const float ss = 2.0f * __sinf(a);
    const float cs = 2.0f * (1.0f - __cosf(a));
    const float vv = vx * vx + vy * vy + vz * vz;   // ~1; keep exact form
    const float R00 = 2.0f + cs * (vx * vx - vv);
    const float R01 = -ss * vz + cs * (vx * vy);
    const float R02 =  ss * vy + cs * (vx * vz);
    const float R10 =  ss * vz + cs * (vy * vx);
    const float R11 = 2.0f + cs * (vy * vy - vv);
    const float R12 = -ss * vx + cs * (vy * vz);
    const float R20 = -ss * vy + cs * (vz * vx);
    const float R21 =  ss * vx + cs * (vz * vy);
    const float R22 = 2.0f + cs * (vz * vz - vv);

    __syncwarp();   // tile writes visible to all lanes

    float* dst = out + n * KVOL;

    #pragma unroll
    for (int q = 0; q < 4; ++q) {
        const int p = lane + 32 * q;
        if (p < KVOL) {
            const float4 b = g_base[p];
            // pixel coords: (grid + 1) * 2 = base . (2R) + 2
            const float x = fmaf(b.x, R00, fmaf(b.y, R10, fmaf(b.z, R20, 2.0f)));
            const float y = fmaf(b.x, R01, fmaf(b.y, R11, fmaf(b.z, R21, 2.0f)));
            const float z = fmaf(b.x, R02, fmaf(b.y, R12, fmaf(b.z, R22, 2.0f)));

            const int x0 = __float2int_rd(x);
            const int y0 = __float2int_rd(y);
            const int z0 = __float2int_rd(z);
            const float wx = x - (float)x0;
            const float wy = y - (float)y0;
            const float wz = z - (float)z0;

            // Valid iff base cell in [-1,4] per axis; otherwise both taps on
            // that axis are outside [0,4] and the sample is exactly zero.
            const bool ok = ((unsigned)(x0 + 1) <= 5u) &
                            ((unsigned)(y0 + 1) <= 5u) &
                            ((unsigned)(z0 + 1) <= 5u);

            const int xc = min(max(x0, -1), 4) + 1;
            const int yc = min(max(y0, -1), 4) + 1;
            const int zc = min(max(z0, -1), 4) + 1;
            const float* vb = tile + zc * PP + yc * PD + xc;

            const float wx0 = 1.0f - wx, wy0 = 1.0f - wy, wz0 = 1.0f - wz;
            const float c00 = wy0 * wx0, c01 = wy0 * wx;
            const float c10 = wy  * wx0, c11 = wy  * wx;

            const float lo = fmaf(c00, vb[0],      fmaf(c01, vb[1],
                             fmaf(c10, vb[PD],     c11 * vb[PD + 1])));
            const float hi = fmaf(c00, vb[PP],     fmaf(c01, vb[PP + 1],
                             fmaf(c10, vb[PP + PD], c11 * vb[PP + PD + 1])));
            const float r = fmaf(wz0, lo, wz * hi);

            dst[p] = ok ? r : 0.0f;
        }
    }
}

extern "C" void kernel_launch(void* const* d_in, const int* in_sizes, int n_in,
                              void* d_out, int out_size)
{
    const float* vol     = (const float*)d_in[0];  // input_filter [N,5,5,5]
    const float* theta_v = (const float*)d_in[1];  // [N,3]
    const float* theta   = (const float*)d_in[2];  // [N]
    float* out = (float*)d_out;

    const int N = in_sizes[2];                     // theta has N elements
    const int blocks = (N + WPB - 1) / WPB;
    fast_rotation_kernel<<<blocks, TPB>>>(vol, theta_v, theta, out, N);
}